// round 17
// baseline (speedup 1.0000x reference)
#include <cuda_runtime.h>
#include <cuda_fp16.h>
#include <math.h>

// ---------------------------------------------------------------------------
// GlobalMHSAWithPosBias: B=128, C=512, RES=14 (N=196), HEADS=8, hd=64
// Round 17 (= round 16 resubmitted; previous run was an infra failure):
// tcgen05 unavailable (harness targets sm_100 base ISA) — stay on mma.sync.
// Changes vs round 14 (best measured):
//   1. three prologue kernels merged into one (they're independent).
//   2. attn epilogue: smem transpose (reuse Qs, pitch 66) -> coalesced word
//      stores instead of 14.7M scattered 2-byte stores. Same values/rounding.
// NOTE: never pass __device__ symbols from host code (rounds-3/4 bug).
// ---------------------------------------------------------------------------

#define B_    128
#define CIN   512
#define NQ    196
#define NPAD  224          // 4 * 56 = 2 * 112
#define HEADS 8
#define HD    64
#define EPS_  1e-5f

// fp16 operand layouts:
//  g_wh: uint2[pr][256 kp], pr = base + (o>>4)*8 + (o&7); .x=h2 W[o], .y=h2 W[o+8]
//  g_xh/g_att: half2 pairs, idx = ((b*128+sb)*224+n)*2 + hi,
//    sb=(kp>>3)*4+(kp&3), hi=(kp>>2)&1, halves by (c&1)
//  g_qkP: unsigned[b][512][224]; row c>>1 (c<1024: Q then K), word m = h2(c, c+1)
//  g_vh : half[b][512][224]; row c-1024 (V), halves along n
__device__ unsigned g_wh [(size_t)1024 * 256 * 2];
__device__ unsigned g_xh [(size_t)B_ * 128 * NPAD * 2];     // BSS 0 (pad cols)
__device__ unsigned g_att[(size_t)B_ * 128 * NPAD * 2];     // BSS 0
__device__ unsigned g_qkP[(size_t)B_ * 512 * NPAD];
__device__ unsigned short g_vh[(size_t)B_ * 512 * NPAD];
__device__ float    g_biasT[HEADS * NQ * NQ];

// ---------------------------------------------------------------------------
__device__ __forceinline__ void mma_f16(float c[4], const unsigned a[4],
                                        unsigned b0, unsigned b1) {
    asm volatile(
        "mma.sync.aligned.m16n8k16.row.col.f32.f16.f16.f32 "
        "{%0,%1,%2,%3}, {%4,%5,%6,%7}, {%8,%9}, {%0,%1,%2,%3};\n"
        : "+f"(c[0]), "+f"(c[1]), "+f"(c[2]), "+f"(c[3])
        : "r"(a[0]), "r"(a[1]), "r"(a[2]), "r"(a[3]), "r"(b0), "r"(b1));
}

__device__ __forceinline__ void cp16(void* dst, const void* src) {
    unsigned s = (unsigned)__cvta_generic_to_shared(dst);
    asm volatile("cp.async.cg.shared.global [%0], [%1], 16;" :: "r"(s), "l"(src));
}
__device__ __forceinline__ void cp_commit() {
    asm volatile("cp.async.commit_group;");
}
template <int N>
__device__ __forceinline__ void cp_wait() {
    asm volatile("cp.async.wait_group %0;" :: "n"(N));
}

__device__ __forceinline__ unsigned packh2(float lo, float hi) {
    __half2 h = __floats2half2_rn(lo, hi);
    return *(unsigned*)&h;
}

// ---------------------------------------------------------------------------
// merged prologue: [0, R1) cvt_w  [R1, R2) pad_cvt_x  [R2, R3) bias gather
// ---------------------------------------------------------------------------
#define PREP_R1 (4 * CIN * CIN)                    // 1048576
#define PREP_R2 (PREP_R1 + B_ * 128 * NPAD * 2)    // + 7340032
#define PREP_R3 (PREP_R2 + HEADS * NQ * NQ)        // + 307328

__global__ void prep_kernel(const float* __restrict__ qkv_w,
                            const float* __restrict__ proj_w,
                            const float* __restrict__ x,
                            const float* __restrict__ ab,
                            const int*   __restrict__ idxs) {
    int i = blockIdx.x * blockDim.x + threadIdx.x;
    if (i < PREP_R1) {
        // weights -> g_wh pair layout
        const int n1 = 3 * CIN * CIN;
        float v;
        int o, k, basepr;
        if (i < n1) { v = qkv_w[i];       o = i / CIN;        k = i % CIN;        basepr = 0; }
        else        { v = proj_w[i - n1]; o = (i - n1) / CIN; k = (i - n1) % CIN; basepr = 768; }
        int pr   = basepr + (o >> 4) * 8 + (o & 7);
        int comp = (o >> 3) & 1;
        int kp   = k >> 1;
        ((__half*)g_wh)[(size_t)pr * 1024 + kp * 4 + comp * 2 + (k & 1)]
            = __float2half_rn(v);
    } else if (i < PREP_R2) {
        // x -> g_xh pair layout (coalesced over n)
        int j  = i - PREP_R1;
        int hi = j & 1;
        int n  = (j >> 1) % NPAD;
        int r  = (j >> 1) / NPAD;          // b*128 + sb
        if (n >= NQ) return;               // pad cols stay 0 (BSS)
        int b  = r >> 7, sb = r & 127;
        int kp = (sb >> 2) * 8 + hi * 4 + (sb & 3);
        int c  = kp * 2;
        const float* xp = x + ((size_t)b * CIN + c) * NQ + n;
        g_xh[((size_t)r * NPAD + n) * 2 + hi] = packh2(xp[0], xp[NQ]);
    } else if (i < PREP_R3) {
        // bias gather
        int j = i - PREP_R2;
        int stride = (idxs[1] == 0 && idxs[3] == 0) ? 2 : 1;   // int64 detection
        int h = j / (NQ * NQ);
        int jj = j - h * (NQ * NQ);
        g_biasT[j] = ab[h * NQ + idxs[(size_t)jj * stride]];
    }
}

// ---------------------------------------------------------------------------
// fp16 GEMM + fused BN affine; pair-packed operands, 2-stage cp.async, BK=64.
// MODE 0: X=g_xh,  W pr base 0,   Y = g_qkP (o<1024, shfl pair-pack) / g_vh
//         launch_bounds(256,3): reg cap 85 -> 3 blocks/SM (measured win)
// MODE 1: X=g_att, W pr base 768, Y = outp (f32, float2 stores, guarded)
//         launch_bounds(256,2)
// ---------------------------------------------------------------------------
#define WP2 36
#define XP2 116
#define WS_T2 (64 * WP2)
#define XS_T2 (16 * XP2)

template <int MODE>
__global__ __launch_bounds__(256, MODE == 0 ? 3 : 2)
void gemm_f16(const float* __restrict__ gamma, const float* __restrict__ beta,
              const float* __restrict__ mean,  const float* __restrict__ var,
              float* __restrict__ outp) {
    extern __shared__ uint2 smg[];
    uint2* Ws = smg;
    uint2* Xs = smg + 2 * WS_T2;

    const uint2* __restrict__ X2 = (MODE == 0) ? (const uint2*)g_xh
                                               : (const uint2*)g_att;
    const uint2* __restrict__ W2 = (const uint2*)g_wh
                                   + (MODE == 0 ? 0 : (size_t)768 * 256);
    const int Ocnt = (MODE == 0) ? 3 * CIN : CIN;

    const int tid  = threadIdx.x;
    const int lane = tid & 31;
    const int wid  = tid >> 5;
    const int wm   = wid & 3;
    const int n0w  = (wid >> 2) * 56;

    const int b  = blockIdx.z;
    const int o0 = blockIdx.y * 128;
    const int n0 = blockIdx.x * 112;

    const uint2* __restrict__ Wp = W2 + (size_t)(o0 / 2) * 256;
    const uint2* __restrict__ Xp = X2 + ((size_t)b * 128) * NPAD + n0;

    float acc[2][7][4];
#pragma unroll
    for (int i = 0; i < 2; i++)
#pragma unroll
        for (int j = 0; j < 7; j++)
#pragma unroll
            for (int k = 0; k < 4; k++) acc[i][j][k] = 0.f;

    const int row = lane >> 2;
    const int col = lane & 3;

    auto load_tiles = [&](int it, int st) {
        uint2* ws = Ws + st * WS_T2;
        uint2* xs = Xs + st * XS_T2;
#pragma unroll
        for (int i = tid; i < 1024; i += 256) {
            int r = i >> 4, c2 = (i & 15) * 2;
            cp16(ws + r * WP2 + c2, Wp + (size_t)r * 256 + it * 32 + c2);
        }
#pragma unroll
        for (int i = tid; i < 896; i += 256) {
            int r = i / 56, c2 = (i % 56) * 2;
            cp16(xs + r * XP2 + c2, Xp + (size_t)(it * 16 + r) * NPAD + c2);
        }
        cp_commit();
    };

    load_tiles(0, 0);

    for (int it = 0; it < 8; ++it) {
        const int cur = it & 1;
        if (it + 1 < 8) {
            load_tiles(it + 1, (it + 1) & 1);
            cp_wait<1>();
        } else {
            cp_wait<0>();
        }
        __syncthreads();

        const uint2* ws = Ws + cur * WS_T2;
        const uint2* xs = Xs + cur * XS_T2;
#pragma unroll
        for (int ks = 0; ks < 4; ks++) {
            unsigned a[2][4];
#pragma unroll
            for (int mt = 0; mt < 2; mt++) {
                int pr = (wm * 2 + mt) * 8 + row;
                uint2 A01 = ws[pr * WP2 + ks * 8 + col];
                uint2 A23 = ws[pr * WP2 + ks * 8 + col + 4];
                a[mt][0] = A01.x; a[mt][1] = A01.y;
                a[mt][2] = A23.x; a[mt][3] = A23.y;
            }
#pragma unroll
            for (int nt = 0; nt < 7; nt++) {
                uint2 Bf = xs[(ks * 4 + col) * XP2 + n0w + nt * 8 + row];
                mma_f16(acc[0][nt], a[0], Bf.x, Bf.y);
                mma_f16(acc[1][nt], a[1], Bf.x, Bf.y);
            }
        }
        __syncthreads();
    }

    // epilogue: BN affine + store
    const bool qk = (MODE == 0) && (o0 < 1024);
#pragma unroll
    for (int mt = 0; mt < 2; mt++) {
        int o_a = o0 + wm * 32 + mt * 16 + row;
        int o_b = o_a + 8;
        float inv_a = gamma[o_a] * rsqrtf(var[o_a] + EPS_);
        float sh_a  = beta[o_a] - mean[o_a] * inv_a;
        float inv_b = gamma[o_b] * rsqrtf(var[o_b] + EPS_);
        float sh_b  = beta[o_b] - mean[o_b] * inv_b;
#pragma unroll
        for (int nt = 0; nt < 7; nt++) {
            int c0 = n0 + n0w + nt * 8 + col * 2;
            float y0 = acc[mt][nt][0] * inv_a + sh_a;
            float y1 = acc[mt][nt][1] * inv_a + sh_a;
            float y2 = acc[mt][nt][2] * inv_b + sh_b;
            float y3 = acc[mt][nt][3] * inv_b + sh_b;
            if (MODE == 0) {
                if (qk) {
                    float z0 = __shfl_down_sync(0xffffffffu, y0, 4);
                    float z1 = __shfl_down_sync(0xffffffffu, y1, 4);
                    float z2 = __shfl_down_sync(0xffffffffu, y2, 4);
                    float z3 = __shfl_down_sync(0xffffffffu, y3, 4);
                    if (!(row & 1)) {
                        int prA = o_a >> 1;
                        int prB = prA + 4;
                        uint2 wa = make_uint2(packh2(y0, z0), packh2(y1, z1));
                        uint2 wb = make_uint2(packh2(y2, z2), packh2(y3, z3));
                        *(uint2*)(g_qkP + ((size_t)b * 512 + prA) * NPAD + c0) = wa;
                        *(uint2*)(g_qkP + ((size_t)b * 512 + prB) * NPAD + c0) = wb;
                    }
                } else {
                    int ca = o_a - 1024, cb = o_b - 1024;
                    *(unsigned*)(g_vh + ((size_t)b * 512 + ca) * NPAD + c0)
                        = packh2(y0, y1);
                    *(unsigned*)(g_vh + ((size_t)b * 512 + cb) * NPAD + c0)
                        = packh2(y2, y3);
                }
            } else {
                if (c0 < NQ) {   // NQ even & c0 even
                    float* ya = outp + ((size_t)b * Ocnt + o_a) * NQ;
                    float* yb = outp + ((size_t)b * Ocnt + o_b) * NQ;
                    *(float2*)(ya + c0) = make_float2(y0, y1);
                    *(float2*)(yb + c0) = make_float2(y2, y3);
                }
            }
        }
    }
}

// ---------------------------------------------------------------------------
// fp16 tensor-core attention (round-14 mainloop). New epilogue: GELU'd output
// transposed through smem (reusing the Qs region, pitch 66 halves), then
// written to g_att with coalesced word stores.
// Per (b,h) block the outputs are exactly channels [64h, 64h+64) of g_att[b]:
//   flat_local = n*64 + d in [0,12544); cc_local = flat_local/196,
//   pos = flat_local%196. Word kp_local = cc_local/2 pairs halves (cc, cc+1).
// ---------------------------------------------------------------------------
#define KP2 232
#define VP2 72
#define PP2 20
#define AQS_O 0
#define AKS_O (32 * KP2)
#define AVS_O (2 * 32 * KP2)
#define APT_O (AVS_O + 112 * VP2)
#define ASM_WORDS (APT_O + 14 * 16 * PP2)

__global__ __launch_bounds__(448, 2)
void attn_kernel() {
    extern __shared__ unsigned sm[];
    unsigned* Qs = sm + AQS_O;
    unsigned* Ks = sm + AKS_O;
    unsigned* Vs = sm + AVS_O;
    unsigned* Pt = sm + APT_O;

    const int tid  = threadIdx.x;
    const int lane = tid & 31;
    const int w    = tid >> 5;
    const int row  = lane >> 2;
    const int col  = lane & 3;
    const int b    = blockIdx.x >> 3;
    const int h    = blockIdx.x & 7;
    const int n0   = w * 16;

    const unsigned* __restrict__ qsrc = g_qkP + ((size_t)b * 512 + h * 32) * NPAD;
    const unsigned* __restrict__ ksrc = g_qkP + ((size_t)b * 512 + 256 + h * 32) * NPAD;
    for (int i = tid; i < 32 * NPAD; i += 448) {
        int dp = i / NPAD, m = i - dp * NPAD;
        Qs[dp * KP2 + m] = qsrc[(size_t)dp * NPAD + m];
        Ks[dp * KP2 + m] = ksrc[(size_t)dp * NPAD + m];
    }
    const unsigned short* __restrict__ vsrc = g_vh + ((size_t)b * 512 + h * 64) * NPAD;
    for (int i = tid; i < 64 * 112; i += 448) {
        int d = i / 112, mp = i - d * 112;
        Vs[mp * VP2 + d] = *(const unsigned*)(vsrc + (size_t)d * NPAD + 2 * mp);
    }
    __syncthreads();

    const float* __restrict__ bptr = g_biasT + (size_t)h * NQ * NQ;
    unsigned* ptw = Pt + w * 16 * PP2;
    const int nb_lo = min(n0 + row, NQ - 1);
    const int nb_hi = min(n0 + row + 8, NQ - 1);

    float o[8][4];
#pragma unroll
    for (int i = 0; i < 8; i++)
#pragma unroll
        for (int j = 0; j < 4; j++) o[i][j] = 0.f;
    float ll = 0.f, lh = 0.f;

    float c[4][4];

    auto do_S = [&](int mc) {
        const int m0 = mc * 32;
#pragma unroll
        for (int s = 0; s < 4; s++)
#pragma unroll
            for (int j = 0; j < 4; j++) c[s][j] = 0.f;
#pragma unroll
        for (int t = 0; t < 4; t++) {
            const int qb = (t * 8 + col) * KP2 + n0 + row;
            unsigned a[4];
            a[0] = Qs[qb];
            a[1] = Qs[qb + 8];
            a[2] = Qs[qb + 4 * KP2];
            a[3] = Qs[qb + 4 * KP2 + 8];
#pragma unroll
            for (int s = 0; s < 4; s++) {
                const int kb = (t * 8 + col) * KP2 + m0 + s * 8 + row;
                mma_f16(c[s], a, Ks[kb], Ks[kb + 4 * KP2]);
            }
        }
    };

    auto do_exp = [&](int mc) {
        const int m0 = mc * 32;
#pragma unroll
        for (int s = 0; s < 4; s++) {
            const int m_b = m0 + s * 8 + 2 * col;
            float p0 = 0.f, p1 = 0.f, p2 = 0.f, p3 = 0.f;
            if (m_b < NQ) {
                float2 blo = *(const float2*)(bptr + (size_t)nb_lo * NQ + m_b);
                float2 bhi = *(const float2*)(bptr + (size_t)nb_hi * NQ + m_b);
                p0 = __expf(c[s][0] * 0.125f + blo.x);
                p1 = __expf(c[s][1] * 0.125f + blo.y);
                p2 = __expf(c[s][2] * 0.125f + bhi.x);
                p3 = __expf(c[s][3] * 0.125f + bhi.y);
            }
            ll += p0 + p1;
            lh += p2 + p3;
            ptw[row * PP2 + s * 4 + col]       = packh2(p0, p1);
            ptw[(row + 8) * PP2 + s * 4 + col] = packh2(p2, p3);
        }
    };

    auto do_PV = [&](int mc) {
#pragma unroll
        for (int u = 0; u < 2; u++) {
            unsigned a[4];
            a[0] = ptw[row * PP2 + u * 8 + col];
            a[1] = ptw[(row + 8) * PP2 + u * 8 + col];
            a[2] = ptw[row * PP2 + u * 8 + col + 4];
            a[3] = ptw[(row + 8) * PP2 + u * 8 + col + 4];
#pragma unroll
            for (int nc = 0; nc < 8; nc++) {
                const int vb = (mc * 16 + u * 8 + col) * VP2 + nc * 8 + row;
                mma_f16(o[nc], a, Vs[vb], Vs[vb + 4 * VP2]);
            }
        }
    };

    do_S(0);
    do_exp(0);
    __syncwarp();
    for (int mc = 0; mc < 7; mc++) {
        if (mc < 6) do_S(mc + 1);
        do_PV(mc);
        __syncwarp();
        if (mc < 6) {
            do_exp(mc + 1);
            __syncwarp();
        }
    }

    ll += __shfl_xor_sync(0xffffffffu, ll, 1);
    ll += __shfl_xor_sync(0xffffffffu, ll, 2);
    lh += __shfl_xor_sync(0xffffffffu, lh, 1);
    lh += __shfl_xor_sync(0xffffffffu, lh, 2);
    const float linv_lo = 1.f / ll;
    const float linv_hi = 1.f / lh;

    // ---- epilogue: transpose through smem (reuse Qs region; pitch 66) ----
    __syncthreads();                       // all warps done reading Qs
    __half* smo = (__half*)sm;             // [n][66] halves, n in [0,196)

    const int n_lo = n0 + row;
    const int n_hi = n0 + row + 8;
#pragma unroll
    for (int nc = 0; nc < 8; nc++) {
        int d0 = nc * 8 + 2 * col;
        if (n_lo < NQ) {
            float v0 = o[nc][0] * linv_lo;
            float v1 = o[nc][1] * linv_lo;
            float g0 = 0.5f * v0 * (1.f + erff(v0 * 0.70710678118654752f));
            float g1 = 0.5f * v1 * (1.f + erff(v1 * 0.70710678118654752f));
            *(__half2*)&smo[n_lo * 66 + d0] = __floats2half2_rn(g0, g1);
        }
        if (n_hi < NQ) {
            float v0 = o[nc][2] * linv_hi;
            float v1 = o[nc][3] * linv_hi;
            float g0 = 0.5f * v0 * (1.f + erff(v0 * 0.70710678118654752f));
            float g1 = 0.5f * v1 * (1.f + erff(v1 * 0.70710678118654752f));
            *(__half2*)&smo[n_hi * 66 + d0] = __floats2half2_rn(g0, g1);
        }
    }
    __syncthreads();

    // coalesced store: word wi -> (kp_local, pos)
    const unsigned short* smh = (const unsigned short*)smo;
    for (int wi = tid; wi < 32 * NQ; wi += 448) {
        int kpl = wi / NQ;
        int pos = wi - kpl * NQ;
        int flat0 = kpl * (2 * NQ) + pos;        // cc_local = 2*kpl
        int flat1 = flat0 + NQ;
        unsigned h0 = smh[(flat0 >> 6) * 66 + (flat0 & 63)];
        unsigned h1 = smh[(flat1 >> 6) * 66 + (flat1 & 63)];
        int kpg = h * 32 + kpl;
        int sb  = (kpg >> 3) * 4 + (kpg & 3);
        int hw  = (kpg >> 2) & 1;
        g_att[(((size_t)b * 128 + sb) * NPAD + pos) * 2 + hw] = h0 | (h1 << 16);
    }
}

// ---------------------------------------------------------------------------
extern "C" void kernel_launch(void* const* d_in, const int* in_sizes, int n_in,
                              void* d_out, int out_size) {
    const float* x      = (const float*)d_in[0];
    const float* qkv_w  = (const float*)d_in[1];
    const float* bn1_g  = (const float*)d_in[2];
    const float* bn1_b  = (const float*)d_in[3];
    const float* bn1_m  = (const float*)d_in[4];
    const float* bn1_v  = (const float*)d_in[5];
    const float* proj_w = (const float*)d_in[6];
    const float* bn2_g  = (const float*)d_in[7];
    const float* bn2_b  = (const float*)d_in[8];
    const float* bn2_m  = (const float*)d_in[9];
    const float* bn2_v  = (const float*)d_in[10];
    const float* ab     = (const float*)d_in[11];
    const int*   idxs   = (const int*)d_in[12];
    float* out = (float*)d_out;

    const int smem_gemm = (2 * WS_T2 + 2 * XS_T2) * 8;   // 66560 B
    const int smem_attn = ASM_WORDS * 4;                 // 109568 B
    cudaFuncSetAttribute(gemm_f16<0>,
                         cudaFuncAttributeMaxDynamicSharedMemorySize, smem_gemm);
    cudaFuncSetAttribute(gemm_f16<1>,
                         cudaFuncAttributeMaxDynamicSharedMemorySize, smem_gemm);
    cudaFuncSetAttribute(attn_kernel,
                         cudaFuncAttributeMaxDynamicSharedMemorySize, smem_attn);

    {   // merged prologue (weights + x + bias)
        int total = PREP_R3;
        prep_kernel<<<(total + 255) / 256, 256>>>(qkv_w, proj_w, x, ab, idxs);
    }
    {   // QKV GEMM + BN1 -> g_qkP (Q,K pairs) / g_vh (V rows)
        dim3 grid(NPAD / 112, (3 * CIN) / 128, B_);
        gemm_f16<0><<<grid, 256, smem_gemm>>>(bn1_g, bn1_b, bn1_m, bn1_v, nullptr);
    }
    {   // attention + gelu + scrambled reshape (coalesced epilogue)
        attn_kernel<<<B_ * HEADS, 448, smem_attn>>>();
    }
    {   // proj GEMM + BN2 -> d_out
        dim3 grid(NPAD / 112, CIN / 128, B_);
        gemm_f16<1><<<grid, 256, smem_gemm>>>(bn2_g, bn2_b, bn2_m, bn2_v, out);
    }
}